// round 11
// baseline (speedup 1.0000x reference)
#include <cuda_runtime.h>
#include <cstdint>

#define DIM     64
#define CHUNKS  16            // float4 chunks per row
#define NMAX    100000        // nodes per ntype (static scratch sizing)
#define EMAX    500000        // edges per relation
#define KSLOT   40            // slots per bucket (deg ~Poisson(10))
#define SPILLC  (4 * EMAX)    // spill capacity = all edges (unconditional)

// ---------------------------------------------------------------------------
// scratch (device globals — no runtime allocation)
// ---------------------------------------------------------------------------
__device__ int  g_idx64;                      // 0 = int32 indices, 1 = int64
__device__ int  g_nover;                      // overflow edge count
__device__ int  g_cur[2 * NMAX];              // per-bucket write cursors
__device__ int  g_entries[2 * NMAX * KSLOT];  // src | (tableFlag<<30), slotted
__device__ int2 g_spill[SPILLC];              // (bucket, src|flag<<30)

// ---------------------------------------------------------------------------
__device__ __forceinline__ int load_idx32(const void* p, int i, int idx64) {
    // index values < 2^31: low word suffices for both int32 and int64 layouts
    return idx64 ? ((const int*)p)[2 * i] : ((const int*)p)[i];
}

// ---------------------------------------------------------------------------
// 1) init: zero cursors (int4-vectorized) + overflow count, probe idx width.
//    int64 values in [0,1e5): odd 32-bit words are 0; int32 random: ~never.
// ---------------------------------------------------------------------------
__global__ void init_kernel(int nb4, const unsigned int* __restrict__ s0w) {
    int i = blockIdx.x * blockDim.x + threadIdx.x;
    if (i == 0) {
        bool i64 = (s0w[1] == 0u) && (s0w[3] == 0u) &&
                   (s0w[5] == 0u) && (s0w[7] == 0u);
        g_idx64 = i64 ? 1 : 0;
        g_nover = 0;
    }
    if (i < nb4) reinterpret_cast<int4*>(g_cur)[i] = make_int4(0, 0, 0, 0);
}

// ---------------------------------------------------------------------------
// 2) permute: slot edges into per-bucket regions. gridDim.y = relation.
//    relation -> (dst ntype, src table): r0:(B,e0) r1:(A,e1) r2:(A,e2) r3:(B,e3)
//    bucket b = ntype*nN + dst; bit30 of entry selects table (e2/e3 vs e0/e1).
//    Overflow (pos >= KSLOT) goes to the spill list (sized for ALL edges).
// ---------------------------------------------------------------------------
__global__ void __launch_bounds__(256)
permute_kernel(const void* __restrict__ s0, const void* __restrict__ d0,
               const void* __restrict__ s1, const void* __restrict__ d1,
               const void* __restrict__ s2, const void* __restrict__ d2,
               const void* __restrict__ s3, const void* __restrict__ d3,
               int nE, int nN) {
    int e = blockIdx.x * blockDim.x + threadIdx.x;
    if (e >= nE) return;
    int r = blockIdx.y;

    const void* sp; const void* dp; int ntype; int flag;
    switch (r) {
        case 0:  sp = s0; dp = d0; ntype = 1; flag = 0; break;
        case 1:  sp = s1; dp = d1; ntype = 0; flag = 0; break;
        case 2:  sp = s2; dp = d2; ntype = 0; flag = 1; break;
        default: sp = s3; dp = d3; ntype = 1; flag = 1; break;
    }

    const int idx64 = g_idx64;
    int src = load_idx32(sp, e, idx64);
    int dst = load_idx32(dp, e, idx64);
    int b = ntype * nN + dst;
    int ent = src | (flag << 30);

    int pos = atomicAdd(&g_cur[b], 1);
    if (pos < KSLOT) {
        g_entries[b * KSLOT + pos] = ent;
    } else {
        int spos = atomicAdd(&g_nover, 1);   // spill holds ALL edges worst-case
        g_spill[spos] = make_int2(b, ent);
    }
}

// ---------------------------------------------------------------------------
// 3) accumulate: ONE bucket per WARP. Lane = (half h = lane>>4, chunk c =
//    lane&15). Half 0 accumulates even entries (+bias), half 1 odd entries;
//    4-shuffle combine; lanes 0-15 relu + store. Trip count = ceil(n/2),
//    no intra-warp bucket imbalance. Gather coalescing identical (2 row
//    segments per warp-load).
// ---------------------------------------------------------------------------
__global__ void __launch_bounds__(256)
accum_kernel(const float* __restrict__ e0, const float* __restrict__ e1,
             const float* __restrict__ e2, const float* __restrict__ e3,
             const float4* __restrict__ bias4, float4* __restrict__ out4,
             int nN) {
    int b = (blockIdx.x * blockDim.x + threadIdx.x) >> 5;   // warp id = bucket
    if (b >= 2 * nN) return;                                // whole warp exits
    int lane = threadIdx.x & 31;
    int c = lane & 15;
    int h = lane >> 4;

    const float* t0;
    const float* t1;
    if (b < nN) { t0 = e1; t1 = e2; }      // h_A
    else        { t0 = e0; t1 = e3; }      // h_B

    int n = g_cur[b];
    if (n > KSLOT) n = KSLOT;

    float4 acc = make_float4(0.f, 0.f, 0.f, 0.f);
    if (h == 0) acc = __ldg(&bias4[c]);
    const int* ep = g_entries + b * KSLOT;
    int coff = c * 4;

    #pragma unroll 2
    for (int j = h; j < n; j += 2) {
        int ent = ep[j];
        const float* tb = (ent & (1 << 30)) ? t1 : t0;
        int src = ent & 0x0FFFFFFF;
        const float4 v =
            *reinterpret_cast<const float4*>(tb + (long long)src * DIM + coff);
        acc.x += v.x; acc.y += v.y; acc.z += v.z; acc.w += v.w;
    }

    // overflow path: never taken in practice (one broadcast-cached load)
    int nov = g_nover;
    if (nov > 0) {
        for (int j = h; j < nov; j += 2) {
            int2 se = g_spill[j];
            if (se.x == b) {
                const float* tb = (se.y & (1 << 30)) ? t1 : t0;
                int src = se.y & 0x0FFFFFFF;
                const float4 v =
                    *reinterpret_cast<const float4*>(tb + (long long)src * DIM + coff);
                acc.x += v.x; acc.y += v.y; acc.z += v.z; acc.w += v.w;
            }
        }
    }

    // combine halves (full-mask shuffles after reconvergence)
    acc.x += __shfl_down_sync(0xFFFFFFFFu, acc.x, 16);
    acc.y += __shfl_down_sync(0xFFFFFFFFu, acc.y, 16);
    acc.z += __shfl_down_sync(0xFFFFFFFFu, acc.z, 16);
    acc.w += __shfl_down_sync(0xFFFFFFFFu, acc.w, 16);

    if (h == 0) {
        acc.x = fmaxf(acc.x, 0.f);
        acc.y = fmaxf(acc.y, 0.f);
        acc.z = fmaxf(acc.z, 0.f);
        acc.w = fmaxf(acc.w, 0.f);
        out4[(long long)b * CHUNKS + c] = acc;
    }
}

// ---------------------------------------------------------------------------
// fallback path (atomic scatter, proven) if shapes exceed static scratch
// ---------------------------------------------------------------------------
__global__ void fb_init_kernel(float4* __restrict__ out,
                               const float4* __restrict__ bias4, int n4) {
    int i = blockIdx.x * blockDim.x + threadIdx.x;
    if (i < n4) out[i] = __ldg(&bias4[i & 15]);
}

__global__ void __launch_bounds__(256)
fb_scatter_kernel(const float* __restrict__ e0, const float* __restrict__ e1,
                  const float* __restrict__ e2, const float* __restrict__ e3,
                  const void* __restrict__ s0, const void* __restrict__ d0,
                  const void* __restrict__ s1, const void* __restrict__ d1,
                  const void* __restrict__ s2, const void* __restrict__ d2,
                  const void* __restrict__ s3, const void* __restrict__ d3,
                  float* __restrict__ out, int nE, long long nN) {
    int g = blockIdx.x * blockDim.x + threadIdx.x;
    int edge = g >> 4;
    int c = g & 15;
    if (edge >= nE) return;
    const float* emb; const void* sp; const void* dp; long long off;
    switch (blockIdx.y) {
        case 0:  emb = e0; sp = s0; dp = d0; off = nN * DIM; break;
        case 1:  emb = e1; sp = s1; dp = d1; off = 0;        break;
        case 2:  emb = e2; sp = s2; dp = d2; off = 0;        break;
        default: emb = e3; sp = s3; dp = d3; off = nN * DIM; break;
    }
    const int idx64 = g_idx64;
    long long src = load_idx32(sp, edge, idx64);
    long long dst = load_idx32(dp, edge, idx64);
    const float4 v =
        *reinterpret_cast<const float4*>(emb + src * DIM + (long long)c * 4);
    float* p = out + off + dst * DIM + (long long)c * 4;
    asm volatile("red.global.add.v4.f32 [%0], {%1,%2,%3,%4};"
                 :: "l"(p), "f"(v.x), "f"(v.y), "f"(v.z), "f"(v.w) : "memory");
}

__global__ void fb_relu_kernel(float4* __restrict__ out, int n4) {
    int i = blockIdx.x * blockDim.x + threadIdx.x;
    if (i >= n4) return;
    float4 v = out[i];
    v.x = fmaxf(v.x, 0.f); v.y = fmaxf(v.y, 0.f);
    v.z = fmaxf(v.z, 0.f); v.w = fmaxf(v.w, 0.f);
    out[i] = v;
}

// ---------------------------------------------------------------------------
// kernel_launch — inputs: embed0..3, h_bias, src0,dst0,...,src3,dst3
// ---------------------------------------------------------------------------
extern "C" void kernel_launch(void* const* d_in, const int* in_sizes, int n_in,
                              void* d_out, int out_size) {
    const float* e0 = (const float*)d_in[0];
    const float* e1 = (const float*)d_in[1];
    const float* e2 = (const float*)d_in[2];
    const float* e3 = (const float*)d_in[3];
    const float4* bias4 = (const float4*)d_in[4];

    const int nN = in_sizes[0] / DIM;      // 100000
    const int nE = in_sizes[5];            // 500000
    const int n4 = out_size / 4;           // 2*N*16

    float* out = (float*)d_out;
    const int T = 256;
    const int nb = 2 * nN;

    if (nN <= NMAX && nE <= EMAX && (nb % 4) == 0) {
        // 1) zero cursors (vectorized) + probe
        int nb4 = nb / 4;
        init_kernel<<<(nb4 + T - 1) / T, T>>>(nb4, (const unsigned int*)d_in[5]);
        // 2) slot edges into buckets
        dim3 gperm((nE + T - 1) / T, 4);
        permute_kernel<<<gperm, T>>>(d_in[5], d_in[6], d_in[7], d_in[8],
                                     d_in[9], d_in[10], d_in[11], d_in[12],
                                     nE, nN);
        // 3) gather-accumulate + bias + relu + store (one bucket per warp)
        long long threads = (long long)nb * 32;
        int blocks = (int)((threads + T - 1) / T);
        accum_kernel<<<blocks, T>>>(e0, e1, e2, e3, bias4, (float4*)out, nN);
    } else {
        // fallback: atomic scatter (init probes idx width only)
        init_kernel<<<1, 32>>>(0, (const unsigned int*)d_in[5]);
        fb_init_kernel<<<(n4 + T - 1) / T, T>>>((float4*)out, bias4, n4);
        int work = nE * CHUNKS;
        dim3 grid((work + T - 1) / T, 4);
        fb_scatter_kernel<<<grid, T>>>(e0, e1, e2, e3,
                                       d_in[5], d_in[6], d_in[7], d_in[8],
                                       d_in[9], d_in[10], d_in[11], d_in[12],
                                       out, nE, nN);
        fb_relu_kernel<<<(n4 + T - 1) / T, T>>>((float4*)out, n4);
    }
}

// round 12
// speedup vs baseline: 1.0847x; 1.0847x over previous
#include <cuda_runtime.h>
#include <cstdint>

#define DIM     64
#define CHUNKS  16            // float4 chunks per row
#define NMAX    100000        // nodes per ntype (static scratch sizing)
#define EMAX    500000        // edges per relation
#define KSLOT   40            // slots per bucket (deg ~Poisson(10))
#define SPILLC  (4 * EMAX)    // spill capacity = all edges (unconditional)

// ---------------------------------------------------------------------------
// scratch (device globals — no runtime allocation)
// ---------------------------------------------------------------------------
__device__ int  g_idx64;                      // 0 = int32 indices, 1 = int64
__device__ int  g_nover;                      // overflow edge count
__device__ int  g_cur[2 * NMAX];              // per-bucket write cursors
__device__ int  g_entries[2 * NMAX * KSLOT];  // src | (tableFlag<<30), slotted
__device__ int2 g_spill[SPILLC];              // (bucket, src|flag<<30)

// ---------------------------------------------------------------------------
__device__ __forceinline__ int load_idx32(const void* p, int i, int idx64) {
    // index values < 2^31: low word suffices for both int32 and int64 layouts
    return idx64 ? ((const int*)p)[2 * i] : ((const int*)p)[i];
}

// load indices for edges e and e+1 (e even) with one vector load
__device__ __forceinline__ int2 load_idx_pair(const void* p, int e, int idx64) {
    if (idx64) {
        int4 v = reinterpret_cast<const int4*>(p)[e >> 1];  // words 4e..4e+3
        return make_int2(v.x, v.z);                         // low words
    } else {
        return reinterpret_cast<const int2*>(p)[e >> 1];
    }
}

// ---------------------------------------------------------------------------
// 1) init: zero cursors (int4-vectorized) + overflow count, probe idx width.
//    int64 values in [0,1e5): odd 32-bit words are 0; int32 random: ~never.
// ---------------------------------------------------------------------------
__global__ void init_kernel(int nb4, const unsigned int* __restrict__ s0w) {
    int i = blockIdx.x * blockDim.x + threadIdx.x;
    if (i == 0) {
        bool i64 = (s0w[1] == 0u) && (s0w[3] == 0u) &&
                   (s0w[5] == 0u) && (s0w[7] == 0u);
        g_idx64 = i64 ? 1 : 0;
        g_nover = 0;
    }
    if (i < nb4) reinterpret_cast<int4*>(g_cur)[i] = make_int4(0, 0, 0, 0);
}

// ---------------------------------------------------------------------------
// 2) permute: TWO edges per thread, vectorized index loads, two independent
//    atomic+store chains (MLP=2 on the ATOMG latency). gridDim.y = relation.
//    relation -> (dst ntype, src table): r0:(B,e0) r1:(A,e1) r2:(A,e2) r3:(B,e3)
//    bucket b = ntype*nN + dst; bit30 of entry selects table (e2/e3 vs e0/e1).
//    Overflow (pos >= KSLOT) goes to the spill list (sized for ALL edges).
// ---------------------------------------------------------------------------
__global__ void __launch_bounds__(256)
permute_kernel(const void* __restrict__ s0, const void* __restrict__ d0,
               const void* __restrict__ s1, const void* __restrict__ d1,
               const void* __restrict__ s2, const void* __restrict__ d2,
               const void* __restrict__ s3, const void* __restrict__ d3,
               int nE, int nN) {
    int t = blockIdx.x * blockDim.x + threadIdx.x;
    int e = t * 2;
    if (e >= nE) return;
    int r = blockIdx.y;

    const void* sp; const void* dp; int ntype; int flag;
    switch (r) {
        case 0:  sp = s0; dp = d0; ntype = 1; flag = 0; break;
        case 1:  sp = s1; dp = d1; ntype = 0; flag = 0; break;
        case 2:  sp = s2; dp = d2; ntype = 0; flag = 1; break;
        default: sp = s3; dp = d3; ntype = 1; flag = 1; break;
    }

    const int idx64 = g_idx64;
    const int base  = ntype * nN;
    const int fbit  = flag << 30;

    if (e + 1 < nE) {
        int2 src = load_idx_pair(sp, e, idx64);
        int2 dst = load_idx_pair(dp, e, idx64);

        int b0 = base + dst.x;
        int b1 = base + dst.y;

        // two independent atomic chains — issue both before consuming either
        int pos0 = atomicAdd(&g_cur[b0], 1);
        int pos1 = atomicAdd(&g_cur[b1], 1);

        if (pos0 < KSLOT) {
            g_entries[b0 * KSLOT + pos0] = src.x | fbit;
        } else {
            int spos = atomicAdd(&g_nover, 1);
            g_spill[spos] = make_int2(b0, src.x | fbit);
        }
        if (pos1 < KSLOT) {
            g_entries[b1 * KSLOT + pos1] = src.y | fbit;
        } else {
            int spos = atomicAdd(&g_nover, 1);
            g_spill[spos] = make_int2(b1, src.y | fbit);
        }
    } else {
        // scalar tail (nE odd)
        int src = load_idx32(sp, e, idx64);
        int dst = load_idx32(dp, e, idx64);
        int b = base + dst;
        int pos = atomicAdd(&g_cur[b], 1);
        if (pos < KSLOT) {
            g_entries[b * KSLOT + pos] = src | fbit;
        } else {
            int spos = atomicAdd(&g_nover, 1);
            g_spill[spos] = make_int2(b, src | fbit);
        }
    }
}

// ---------------------------------------------------------------------------
// 3) accumulate (R10 proven version): thread = (bucket, float4-chunk).
//    Seed = bias (broadcast), register-accumulate gathered rows, relu, store.
//    bucket < nN -> h_A (tables e1/e2), else h_B (tables e0/e3).
// ---------------------------------------------------------------------------
__global__ void __launch_bounds__(256)
accum_kernel(const float* __restrict__ e0, const float* __restrict__ e1,
             const float* __restrict__ e2, const float* __restrict__ e3,
             const float4* __restrict__ bias4, float4* __restrict__ out4,
             int nN) {
    int g = blockIdx.x * blockDim.x + threadIdx.x;
    int b = g >> 4;
    int c = g & 15;
    if (b >= 2 * nN) return;

    const float* t0;
    const float* t1;
    if (b < nN) { t0 = e1; t1 = e2; }      // h_A
    else        { t0 = e0; t1 = e3; }      // h_B

    int n = g_cur[b];
    if (n > KSLOT) n = KSLOT;

    float4 acc = __ldg(&bias4[c]);
    const int* ep = g_entries + b * KSLOT;
    int coff = c * 4;

    #pragma unroll 4
    for (int j = 0; j < n; j++) {
        int ent = ep[j];
        const float* tb = (ent & (1 << 30)) ? t1 : t0;
        int src = ent & 0x0FFFFFFF;
        const float4 v =
            *reinterpret_cast<const float4*>(tb + (long long)src * DIM + coff);
        acc.x += v.x; acc.y += v.y; acc.z += v.z; acc.w += v.w;
    }

    // overflow path: never taken in practice (one broadcast-cached load)
    int nov = g_nover;
    if (nov > 0) {
        for (int j = 0; j < nov; j++) {
            int2 se = g_spill[j];
            if (se.x == b) {
                const float* tb = (se.y & (1 << 30)) ? t1 : t0;
                int src = se.y & 0x0FFFFFFF;
                const float4 v =
                    *reinterpret_cast<const float4*>(tb + (long long)src * DIM + coff);
                acc.x += v.x; acc.y += v.y; acc.z += v.z; acc.w += v.w;
            }
        }
    }

    acc.x = fmaxf(acc.x, 0.f);
    acc.y = fmaxf(acc.y, 0.f);
    acc.z = fmaxf(acc.z, 0.f);
    acc.w = fmaxf(acc.w, 0.f);
    out4[(long long)b * CHUNKS + c] = acc;
}

// ---------------------------------------------------------------------------
// fallback path (atomic scatter, proven) if shapes exceed static scratch
// ---------------------------------------------------------------------------
__global__ void fb_init_kernel(float4* __restrict__ out,
                               const float4* __restrict__ bias4, int n4) {
    int i = blockIdx.x * blockDim.x + threadIdx.x;
    if (i < n4) out[i] = __ldg(&bias4[i & 15]);
}

__global__ void __launch_bounds__(256)
fb_scatter_kernel(const float* __restrict__ e0, const float* __restrict__ e1,
                  const float* __restrict__ e2, const float* __restrict__ e3,
                  const void* __restrict__ s0, const void* __restrict__ d0,
                  const void* __restrict__ s1, const void* __restrict__ d1,
                  const void* __restrict__ s2, const void* __restrict__ d2,
                  const void* __restrict__ s3, const void* __restrict__ d3,
                  float* __restrict__ out, int nE, long long nN) {
    int g = blockIdx.x * blockDim.x + threadIdx.x;
    int edge = g >> 4;
    int c = g & 15;
    if (edge >= nE) return;
    const float* emb; const void* sp; const void* dp; long long off;
    switch (blockIdx.y) {
        case 0:  emb = e0; sp = s0; dp = d0; off = nN * DIM; break;
        case 1:  emb = e1; sp = s1; dp = d1; off = 0;        break;
        case 2:  emb = e2; sp = s2; dp = d2; off = 0;        break;
        default: emb = e3; sp = s3; dp = d3; off = nN * DIM; break;
    }
    const int idx64 = g_idx64;
    long long src = load_idx32(sp, edge, idx64);
    long long dst = load_idx32(dp, edge, idx64);
    const float4 v =
        *reinterpret_cast<const float4*>(emb + src * DIM + (long long)c * 4);
    float* p = out + off + dst * DIM + (long long)c * 4;
    asm volatile("red.global.add.v4.f32 [%0], {%1,%2,%3,%4};"
                 :: "l"(p), "f"(v.x), "f"(v.y), "f"(v.z), "f"(v.w) : "memory");
}

__global__ void fb_relu_kernel(float4* __restrict__ out, int n4) {
    int i = blockIdx.x * blockDim.x + threadIdx.x;
    if (i >= n4) return;
    float4 v = out[i];
    v.x = fmaxf(v.x, 0.f); v.y = fmaxf(v.y, 0.f);
    v.z = fmaxf(v.z, 0.f); v.w = fmaxf(v.w, 0.f);
    out[i] = v;
}

// ---------------------------------------------------------------------------
// kernel_launch — inputs: embed0..3, h_bias, src0,dst0,...,src3,dst3
// ---------------------------------------------------------------------------
extern "C" void kernel_launch(void* const* d_in, const int* in_sizes, int n_in,
                              void* d_out, int out_size) {
    const float* e0 = (const float*)d_in[0];
    const float* e1 = (const float*)d_in[1];
    const float* e2 = (const float*)d_in[2];
    const float* e3 = (const float*)d_in[3];
    const float4* bias4 = (const float4*)d_in[4];

    const int nN = in_sizes[0] / DIM;      // 100000
    const int nE = in_sizes[5];            // 500000
    const int n4 = out_size / 4;           // 2*N*16

    float* out = (float*)d_out;
    const int T = 256;
    const int nb = 2 * nN;

    if (nN <= NMAX && nE <= EMAX && (nb % 4) == 0) {
        // 1) zero cursors (vectorized) + probe
        int nb4 = nb / 4;
        init_kernel<<<(nb4 + T - 1) / T, T>>>(nb4, (const unsigned int*)d_in[5]);
        // 2) slot edges into buckets (2 edges per thread)
        int nPairs = (nE + 1) / 2;
        dim3 gperm((nPairs + T - 1) / T, 4);
        permute_kernel<<<gperm, T>>>(d_in[5], d_in[6], d_in[7], d_in[8],
                                     d_in[9], d_in[10], d_in[11], d_in[12],
                                     nE, nN);
        // 3) gather-accumulate + bias + relu + store
        int work = nb * CHUNKS;
        accum_kernel<<<(work + T - 1) / T, T>>>(e0, e1, e2, e3, bias4,
                                                (float4*)out, nN);
    } else {
        // fallback: atomic scatter (init probes idx width only)
        init_kernel<<<1, 32>>>(0, (const unsigned int*)d_in[5]);
        fb_init_kernel<<<(n4 + T - 1) / T, T>>>((float4*)out, bias4, n4);
        int work = nE * CHUNKS;
        dim3 grid((work + T - 1) / T, 4);
        fb_scatter_kernel<<<grid, T>>>(e0, e1, e2, e3,
                                       d_in[5], d_in[6], d_in[7], d_in[8],
                                       d_in[9], d_in[10], d_in[11], d_in[12],
                                       out, nE, nN);
        fb_relu_kernel<<<(n4 + T - 1) / T, T>>>((float4*)out, n4);
    }
}

// round 13
// speedup vs baseline: 1.1900x; 1.0970x over previous
#include <cuda_runtime.h>
#include <cstdint>

#define DIM     64
#define CHUNKS  16            // float4 chunks per row
#define NMAX    100000        // nodes per ntype (static scratch sizing)
#define EMAX    500000        // edges per relation
#define KSLOT   40            // slots per bucket (deg ~Poisson(10)); 160B, 16B-aligned
#define SPILLC  (4 * EMAX)    // spill capacity = all edges (unconditional)
#define NOVER_IDX (2 * NMAX)  // overflow counter lives at g_cur[NOVER_IDX]

// ---------------------------------------------------------------------------
// scratch (device globals — no runtime allocation). g_cur[0..2*NMAX) are the
// per-bucket cursors; g_cur[2*NMAX] is the overflow count. One memset clears
// everything before permute.
// ---------------------------------------------------------------------------
__device__ int  g_cur[2 * NMAX + 1];
__device__ int  g_entries[2 * NMAX * KSLOT];  // src | (tableFlag<<30), slotted
__device__ int2 g_spill[SPILLC];              // (bucket, src|flag<<30)

// ---------------------------------------------------------------------------
// index helpers. int64 values in [0,1e5): odd 32-bit words are 0.
// int32 random values: P(4 specific words all 0) ~ 1e-20. Broadcast loads.
// ---------------------------------------------------------------------------
__device__ __forceinline__ int probe_idx64(const unsigned int* __restrict__ w) {
    return ((w[1] | w[3] | w[5] | w[7]) == 0u) ? 1 : 0;
}
__device__ __forceinline__ int load_idx32(const void* p, int i, int idx64) {
    // index values < 2^31: low word suffices for both int32 and int64 layouts
    return idx64 ? ((const int*)p)[2 * i] : ((const int*)p)[i];
}

// ---------------------------------------------------------------------------
// 1) permute: slot edges into per-bucket regions. gridDim.y = relation.
//    relation -> (dst ntype, src table): r0:(B,e0) r1:(A,e1) r2:(A,e2) r3:(B,e3)
//    bucket b = ntype*nN + dst; bit30 of entry selects table (e2/e3 vs e0/e1).
//    Overflow (pos >= KSLOT) goes to the spill list (sized for ALL edges).
// ---------------------------------------------------------------------------
__global__ void __launch_bounds__(256)
permute_kernel(const void* __restrict__ s0, const void* __restrict__ d0,
               const void* __restrict__ s1, const void* __restrict__ d1,
               const void* __restrict__ s2, const void* __restrict__ d2,
               const void* __restrict__ s3, const void* __restrict__ d3,
               int nE, int nN) {
    int e = blockIdx.x * blockDim.x + threadIdx.x;
    if (e >= nE) return;
    int r = blockIdx.y;

    const void* sp; const void* dp; int ntype; int flag;
    switch (r) {
        case 0:  sp = s0; dp = d0; ntype = 1; flag = 0; break;
        case 1:  sp = s1; dp = d1; ntype = 0; flag = 0; break;
        case 2:  sp = s2; dp = d2; ntype = 0; flag = 1; break;
        default: sp = s3; dp = d3; ntype = 1; flag = 1; break;
    }

    const int idx64 = probe_idx64((const unsigned int*)s0);
    int src = load_idx32(sp, e, idx64);
    int dst = load_idx32(dp, e, idx64);
    int b = ntype * nN + dst;
    int ent = src | (flag << 30);

    int pos = atomicAdd(&g_cur[b], 1);
    if (pos < KSLOT) {
        g_entries[b * KSLOT + pos] = ent;
    } else {
        int spos = atomicAdd(&g_cur[NOVER_IDX], 1);
        g_spill[spos] = make_int2(b, ent);
    }
}

// ---------------------------------------------------------------------------
// 2) accumulate: thread = (bucket, float4-chunk). Seed = bias (broadcast),
//    register-accumulate gathered rows, relu, single store.
//    bucket < nN -> h_A (tables e1/e2), else h_B (tables e0/e3).
//    Entries fetched 4-at-a-time via int4 (bucket regions are 16B-aligned);
//    slots >= n are valid memory, predicated out of the accumulation.
// ---------------------------------------------------------------------------
__global__ void __launch_bounds__(256)
accum_kernel(const float* __restrict__ e0, const float* __restrict__ e1,
             const float* __restrict__ e2, const float* __restrict__ e3,
             const float4* __restrict__ bias4, float4* __restrict__ out4,
             int nN) {
    int g = blockIdx.x * blockDim.x + threadIdx.x;
    int b = g >> 4;
    int c = g & 15;
    if (b >= 2 * nN) return;

    const float* t0;
    const float* t1;
    if (b < nN) { t0 = e1; t1 = e2; }      // h_A
    else        { t0 = e0; t1 = e3; }      // h_B

    int n = g_cur[b];
    if (n > KSLOT) n = KSLOT;

    float4 acc = __ldg(&bias4[c]);
    const int4* ep4 = reinterpret_cast<const int4*>(g_entries + b * KSLOT);
    int coff = c * 4;

    for (int j = 0; j < n; j += 4) {
        int4 e4 = ep4[j >> 2];
        int ents[4] = {e4.x, e4.y, e4.z, e4.w};
        #pragma unroll
        for (int k = 0; k < 4; k++) {
            if (j + k < n) {
                int ent = ents[k];
                const float* tb = (ent & (1 << 30)) ? t1 : t0;
                int src = ent & 0x0FFFFFFF;
                const float4 v = *reinterpret_cast<const float4*>(
                    tb + (long long)src * DIM + coff);
                acc.x += v.x; acc.y += v.y; acc.z += v.z; acc.w += v.w;
            }
        }
    }

    // overflow path: never taken in practice (one broadcast-cached load)
    int nov = g_cur[NOVER_IDX];
    if (nov > 0) {
        for (int j = 0; j < nov; j++) {
            int2 se = g_spill[j];
            if (se.x == b) {
                const float* tb = (se.y & (1 << 30)) ? t1 : t0;
                int src = se.y & 0x0FFFFFFF;
                const float4 v = *reinterpret_cast<const float4*>(
                    tb + (long long)src * DIM + coff);
                acc.x += v.x; acc.y += v.y; acc.z += v.z; acc.w += v.w;
            }
        }
    }

    acc.x = fmaxf(acc.x, 0.f);
    acc.y = fmaxf(acc.y, 0.f);
    acc.z = fmaxf(acc.z, 0.f);
    acc.w = fmaxf(acc.w, 0.f);
    out4[(long long)b * CHUNKS + c] = acc;
}

// ---------------------------------------------------------------------------
// fallback path (atomic scatter, proven) if shapes exceed static scratch.
// Does not touch the bucket scratch at all.
// ---------------------------------------------------------------------------
__global__ void fb_init_kernel(float4* __restrict__ out,
                               const float4* __restrict__ bias4, int n4) {
    int i = blockIdx.x * blockDim.x + threadIdx.x;
    if (i < n4) out[i] = __ldg(&bias4[i & 15]);
}

__global__ void __launch_bounds__(256)
fb_scatter_kernel(const float* __restrict__ e0, const float* __restrict__ e1,
                  const float* __restrict__ e2, const float* __restrict__ e3,
                  const void* __restrict__ s0, const void* __restrict__ d0,
                  const void* __restrict__ s1, const void* __restrict__ d1,
                  const void* __restrict__ s2, const void* __restrict__ d2,
                  const void* __restrict__ s3, const void* __restrict__ d3,
                  float* __restrict__ out, int nE, long long nN) {
    int g = blockIdx.x * blockDim.x + threadIdx.x;
    int edge = g >> 4;
    int c = g & 15;
    if (edge >= nE) return;
    const float* emb; const void* sp; const void* dp; long long off;
    switch (blockIdx.y) {
        case 0:  emb = e0; sp = s0; dp = d0; off = nN * DIM; break;
        case 1:  emb = e1; sp = s1; dp = d1; off = 0;        break;
        case 2:  emb = e2; sp = s2; dp = d2; off = 0;        break;
        default: emb = e3; sp = s3; dp = d3; off = nN * DIM; break;
    }
    const int idx64 = probe_idx64((const unsigned int*)s0);
    long long src = load_idx32(sp, edge, idx64);
    long long dst = load_idx32(dp, edge, idx64);
    const float4 v =
        *reinterpret_cast<const float4*>(emb + src * DIM + (long long)c * 4);
    float* p = out + off + dst * DIM + (long long)c * 4;
    asm volatile("red.global.add.v4.f32 [%0], {%1,%2,%3,%4};"
                 :: "l"(p), "f"(v.x), "f"(v.y), "f"(v.z), "f"(v.w) : "memory");
}

__global__ void fb_relu_kernel(float4* __restrict__ out, int n4) {
    int i = blockIdx.x * blockDim.x + threadIdx.x;
    if (i >= n4) return;
    float4 v = out[i];
    v.x = fmaxf(v.x, 0.f); v.y = fmaxf(v.y, 0.f);
    v.z = fmaxf(v.z, 0.f); v.w = fmaxf(v.w, 0.f);
    out[i] = v;
}

// ---------------------------------------------------------------------------
// kernel_launch — inputs: embed0..3, h_bias, src0,dst0,...,src3,dst3
// ---------------------------------------------------------------------------
extern "C" void kernel_launch(void* const* d_in, const int* in_sizes, int n_in,
                              void* d_out, int out_size) {
    const float* e0 = (const float*)d_in[0];
    const float* e1 = (const float*)d_in[1];
    const float* e2 = (const float*)d_in[2];
    const float* e3 = (const float*)d_in[3];
    const float4* bias4 = (const float4*)d_in[4];

    const int nN = in_sizes[0] / DIM;      // 100000
    const int nE = in_sizes[5];            // 500000
    const int n4 = out_size / 4;           // 2*N*16

    float* out = (float*)d_out;
    const int T = 256;
    const int nb = 2 * nN;

    if (nN <= NMAX && nE <= EMAX) {
        // 1) zero cursors + overflow count with one async memset (graph
        //    memset node — no kernel launch, no allocation)
        void* curAddr = nullptr;
        cudaGetSymbolAddress(&curAddr, g_cur);
        cudaMemsetAsync(curAddr, 0, (size_t)(2 * NMAX + 1) * sizeof(int), 0);

        // 2) slot edges into buckets
        dim3 gperm((nE + T - 1) / T, 4);
        permute_kernel<<<gperm, T>>>(d_in[5], d_in[6], d_in[7], d_in[8],
                                     d_in[9], d_in[10], d_in[11], d_in[12],
                                     nE, nN);
        // 3) gather-accumulate + bias + relu + store
        int work = nb * CHUNKS;
        accum_kernel<<<(work + T - 1) / T, T>>>(e0, e1, e2, e3, bias4,
                                                (float4*)out, nN);
    } else {
        // fallback: atomic scatter
        fb_init_kernel<<<(n4 + T - 1) / T, T>>>((float4*)out, bias4, n4);
        int work = nE * CHUNKS;
        dim3 grid((work + T - 1) / T, 4);
        fb_scatter_kernel<<<grid, T>>>(e0, e1, e2, e3,
                                       d_in[5], d_in[6], d_in[7], d_in[8],
                                       d_in[9], d_in[10], d_in[11], d_in[12],
                                       out, nE, nN);
        fb_relu_kernel<<<(n4 + T - 1) / T, T>>>((float4*)out, n4);
    }
}

// round 14
// speedup vs baseline: 1.2079x; 1.0151x over previous
#include <cuda_runtime.h>
#include <cstdint>

#define DIM     64
#define CHUNKS  16            // float4 chunks per row
#define NMAX    100000        // nodes per ntype (static scratch sizing)
#define EMAX    500000        // edges per relation
#define KSLOT   40            // slots per bucket (deg ~Poisson(10)); 160B, 16B-aligned
#define SPILLC  (4 * EMAX)    // spill capacity = all edges (unconditional)
#define NOVER_IDX (2 * NMAX)  // overflow counter lives at g_cur[NOVER_IDX]

// entry encoding: bits [8..27] = src*256 (byte offset into embed table),
//                 bit 30 = table flag. Requires src*256 < 2^28 (N < 1M).
#define ENT_OFF_MASK 0x0FFFFFFF
#define ENT_FLAG_BIT (1 << 30)

// ---------------------------------------------------------------------------
// scratch (device globals — no runtime allocation). g_cur[0..2*NMAX) are the
// per-bucket cursors; g_cur[2*NMAX] is the overflow count. One memset clears
// everything before permute.
// ---------------------------------------------------------------------------
__device__ int  g_cur[2 * NMAX + 1];
__device__ int  g_entries[2 * NMAX * KSLOT];  // (src<<8) | (flag<<30), slotted
__device__ int2 g_spill[SPILLC];              // (bucket, entry)

// ---------------------------------------------------------------------------
// index helpers. int64 values in [0,1e5): odd 32-bit words are 0.
// int32 random values: P(4 specific words all 0) ~ 1e-20. Broadcast loads.
// ---------------------------------------------------------------------------
__device__ __forceinline__ int probe_idx64(const unsigned int* __restrict__ w) {
    return ((w[1] | w[3] | w[5] | w[7]) == 0u) ? 1 : 0;
}
__device__ __forceinline__ int load_idx32(const void* p, int i, int idx64) {
    // index values < 2^31: low word suffices for both int32 and int64 layouts
    return idx64 ? ((const int*)p)[2 * i] : ((const int*)p)[i];
}

// ---------------------------------------------------------------------------
// 1) permute: slot edges into per-bucket regions. gridDim.y = relation.
//    relation -> (dst ntype, src table): r0:(B,e0) r1:(A,e1) r2:(A,e2) r3:(B,e3)
//    bucket b = ntype*nN + dst; entry carries precomputed byte offset + flag.
//    Overflow (pos >= KSLOT) goes to the spill list (sized for ALL edges).
// ---------------------------------------------------------------------------
__global__ void __launch_bounds__(256)
permute_kernel(const void* __restrict__ s0, const void* __restrict__ d0,
               const void* __restrict__ s1, const void* __restrict__ d1,
               const void* __restrict__ s2, const void* __restrict__ d2,
               const void* __restrict__ s3, const void* __restrict__ d3,
               int nE, int nN) {
    int e = blockIdx.x * blockDim.x + threadIdx.x;
    if (e >= nE) return;
    int r = blockIdx.y;

    const void* sp; const void* dp; int ntype; int flag;
    switch (r) {
        case 0:  sp = s0; dp = d0; ntype = 1; flag = 0; break;
        case 1:  sp = s1; dp = d1; ntype = 0; flag = 0; break;
        case 2:  sp = s2; dp = d2; ntype = 0; flag = 1; break;
        default: sp = s3; dp = d3; ntype = 1; flag = 1; break;
    }

    const int idx64 = probe_idx64((const unsigned int*)s0);
    int src = load_idx32(sp, e, idx64);
    int dst = load_idx32(dp, e, idx64);
    int b = ntype * nN + dst;
    int ent = (src << 8) | (flag << 30);   // byte offset (src*256) + table flag

    int pos = atomicAdd(&g_cur[b], 1);
    if (pos < KSLOT) {
        g_entries[b * KSLOT + pos] = ent;
    } else {
        int spos = atomicAdd(&g_cur[NOVER_IDX], 1);
        g_spill[spos] = make_int2(b, ent);
    }
}

// ---------------------------------------------------------------------------
// 2) accumulate: thread = (bucket, float4-chunk). Seed = bias (broadcast),
//    register-accumulate gathered rows, relu, single streaming store.
//    bucket < nN -> h_A (tables e1/e2), else h_B (tables e0/e3).
//    Entries fetched 4-at-a-time via int4; entry already holds the row byte
//    offset, so the gather address is a single LEA. Output stored with .cs
//    (write-once) to avoid evicting embed-table lines from L2.
// ---------------------------------------------------------------------------
__global__ void __launch_bounds__(256)
accum_kernel(const float* __restrict__ e0, const float* __restrict__ e1,
             const float* __restrict__ e2, const float* __restrict__ e3,
             const float4* __restrict__ bias4, float4* __restrict__ out4,
             int nN) {
    int g = blockIdx.x * blockDim.x + threadIdx.x;
    int b = g >> 4;
    int c = g & 15;
    if (b >= 2 * nN) return;

    const char* t0;
    const char* t1;
    if (b < nN) { t0 = (const char*)e1; t1 = (const char*)e2; }  // h_A
    else        { t0 = (const char*)e0; t1 = (const char*)e3; }  // h_B

    int n = g_cur[b];
    if (n > KSLOT) n = KSLOT;

    float4 acc = __ldg(&bias4[c]);
    const int4* ep4 = reinterpret_cast<const int4*>(g_entries + b * KSLOT);
    int coff = c << 4;                     // c * 16 bytes

    for (int j = 0; j < n; j += 4) {
        int4 e4 = ep4[j >> 2];
        int ents[4] = {e4.x, e4.y, e4.z, e4.w};
        #pragma unroll
        for (int k = 0; k < 4; k++) {
            if (j + k < n) {
                int ent = ents[k];
                const char* tb = (ent & ENT_FLAG_BIT) ? t1 : t0;
                const float4 v = *reinterpret_cast<const float4*>(
                    tb + (ent & ENT_OFF_MASK) + coff);
                acc.x += v.x; acc.y += v.y; acc.z += v.z; acc.w += v.w;
            }
        }
    }

    // overflow path: never taken in practice (one broadcast-cached load)
    int nov = g_cur[NOVER_IDX];
    if (nov > 0) {
        for (int j = 0; j < nov; j++) {
            int2 se = g_spill[j];
            if (se.x == b) {
                const char* tb = (se.y & ENT_FLAG_BIT) ? t1 : t0;
                const float4 v = *reinterpret_cast<const float4*>(
                    tb + (se.y & ENT_OFF_MASK) + coff);
                acc.x += v.x; acc.y += v.y; acc.z += v.z; acc.w += v.w;
            }
        }
    }

    acc.x = fmaxf(acc.x, 0.f);
    acc.y = fmaxf(acc.y, 0.f);
    acc.z = fmaxf(acc.z, 0.f);
    acc.w = fmaxf(acc.w, 0.f);
    __stcs(&out4[(long long)b * CHUNKS + c], acc);   // write-once output
}

// ---------------------------------------------------------------------------
// fallback path (atomic scatter, proven) if shapes exceed static scratch.
// Does not touch the bucket scratch at all.
// ---------------------------------------------------------------------------
__global__ void fb_init_kernel(float4* __restrict__ out,
                               const float4* __restrict__ bias4, int n4) {
    int i = blockIdx.x * blockDim.x + threadIdx.x;
    if (i < n4) out[i] = __ldg(&bias4[i & 15]);
}

__global__ void __launch_bounds__(256)
fb_scatter_kernel(const float* __restrict__ e0, const float* __restrict__ e1,
                  const float* __restrict__ e2, const float* __restrict__ e3,
                  const void* __restrict__ s0, const void* __restrict__ d0,
                  const void* __restrict__ s1, const void* __restrict__ d1,
                  const void* __restrict__ s2, const void* __restrict__ d2,
                  const void* __restrict__ s3, const void* __restrict__ d3,
                  float* __restrict__ out, int nE, long long nN) {
    int g = blockIdx.x * blockDim.x + threadIdx.x;
    int edge = g >> 4;
    int c = g & 15;
    if (edge >= nE) return;
    const float* emb; const void* sp; const void* dp; long long off;
    switch (blockIdx.y) {
        case 0:  emb = e0; sp = s0; dp = d0; off = nN * DIM; break;
        case 1:  emb = e1; sp = s1; dp = d1; off = 0;        break;
        case 2:  emb = e2; sp = s2; dp = d2; off = 0;        break;
        default: emb = e3; sp = s3; dp = d3; off = nN * DIM; break;
    }
    const int idx64 = probe_idx64((const unsigned int*)s0);
    long long src = load_idx32(sp, edge, idx64);
    long long dst = load_idx32(dp, edge, idx64);
    const float4 v =
        *reinterpret_cast<const float4*>(emb + src * DIM + (long long)c * 4);
    float* p = out + off + dst * DIM + (long long)c * 4;
    asm volatile("red.global.add.v4.f32 [%0], {%1,%2,%3,%4};"
                 :: "l"(p), "f"(v.x), "f"(v.y), "f"(v.z), "f"(v.w) : "memory");
}

__global__ void fb_relu_kernel(float4* __restrict__ out, int n4) {
    int i = blockIdx.x * blockDim.x + threadIdx.x;
    if (i >= n4) return;
    float4 v = out[i];
    v.x = fmaxf(v.x, 0.f); v.y = fmaxf(v.y, 0.f);
    v.z = fmaxf(v.z, 0.f); v.w = fmaxf(v.w, 0.f);
    out[i] = v;
}

// ---------------------------------------------------------------------------
// kernel_launch — inputs: embed0..3, h_bias, src0,dst0,...,src3,dst3
// ---------------------------------------------------------------------------
extern "C" void kernel_launch(void* const* d_in, const int* in_sizes, int n_in,
                              void* d_out, int out_size) {
    const float* e0 = (const float*)d_in[0];
    const float* e1 = (const float*)d_in[1];
    const float* e2 = (const float*)d_in[2];
    const float* e3 = (const float*)d_in[3];
    const float4* bias4 = (const float4*)d_in[4];

    const int nN = in_sizes[0] / DIM;      // 100000
    const int nE = in_sizes[5];            // 500000
    const int n4 = out_size / 4;           // 2*N*16

    float* out = (float*)d_out;
    const int T = 256;
    const int nb = 2 * nN;

    // entry encoding requires src*256 < 2^28
    if (nN <= NMAX && nE <= EMAX && nN < (1 << 20)) {
        // 1) zero cursors + overflow count with one async memset (graph
        //    memset node — no kernel launch, no allocation)
        void* curAddr = nullptr;
        cudaGetSymbolAddress(&curAddr, g_cur);
        cudaMemsetAsync(curAddr, 0, (size_t)(2 * NMAX + 1) * sizeof(int), 0);

        // 2) slot edges into buckets
        dim3 gperm((nE + T - 1) / T, 4);
        permute_kernel<<<gperm, T>>>(d_in[5], d_in[6], d_in[7], d_in[8],
                                     d_in[9], d_in[10], d_in[11], d_in[12],
                                     nE, nN);
        // 3) gather-accumulate + bias + relu + store
        int work = nb * CHUNKS;
        accum_kernel<<<(work + T - 1) / T, T>>>(e0, e1, e2, e3, bias4,
                                                (float4*)out, nN);
    } else {
        // fallback: atomic scatter
        fb_init_kernel<<<(n4 + T - 1) / T, T>>>((float4*)out, bias4, n4);
        int work = nE * CHUNKS;
        dim3 grid((work + T - 1) / T, 4);
        fb_scatter_kernel<<<grid, T>>>(e0, e1, e2, e3,
                                       d_in[5], d_in[6], d_in[7], d_in[8],
                                       d_in[9], d_in[10], d_in[11], d_in[12],
                                       out, nE, nN);
        fb_relu_kernel<<<(n4 + T - 1) / T, T>>>((float4*)out, n4);
    }
}